// round 2
// baseline (speedup 1.0000x reference)
#include <cuda_runtime.h>
#include <cuda_bf16.h>

// Decoder_2430951489916 — fully fused single-kernel version.
//   B=4, N=512, M=512, ZD=128, YD=2, XD=1
// Inputs (metadata order): t (B,N,1) f32, z (B,N,128) f32, x (B,M,1) f32,
//                          sigma (128,) f32, W (2,128) f32, b (2,) f32
// Output: (B, M, 2) f32.
//
// out[b,m,y] = b_y + sum_n sum_c W[y,c]*z[b,n,c]*exp(-0.5*((x_m-t_n)*exp(-sigma_c))^2)
// Fast path (all sigma equal — true for bench inputs):
//   out[b,m,y] = b_y + sum_n exp(coef*(x_m-t_n)^2) * zw[b,n,y],  zw = z @ W^T,
//   coef = -0.5*exp(-2*sigma_0).
// Each block recomputes zw for its batch into smem (16x redundancy, cheap)
// so everything is one launch — the 2-kernel version was launch-overhead bound.

#define BB 4
#define NN 512
#define MM 512
#define ZDIM 128
#define YDIM 2
#define GPB 16                 // blocks per batch
#define MPB (MM / GPB)         // 32 m-points per block
#define NTHREADS 512

__global__ __launch_bounds__(NTHREADS) void decoder_fused_kernel(
    const float* __restrict__ t,
    const float* __restrict__ z,
    const float* __restrict__ x,
    const float* __restrict__ sigma,
    const float* __restrict__ W,
    const float* __restrict__ bias,
    float* __restrict__ out) {
    __shared__ float t_s[NN];
    __shared__ float zw0_s[NN];
    __shared__ float zw1_s[NN];
    __shared__ float W_s[YDIM * ZDIM];
    __shared__ int nonuniform;

    const int tid   = threadIdx.x;
    const int b     = blockIdx.x / GPB;
    const int mbase = (blockIdx.x % GPB) * MPB;

    if (tid == 0) nonuniform = 0;
    if (tid < NN)          t_s[tid] = t[b * NN + tid];        // XD == 1
    if (tid < YDIM * ZDIM) W_s[tid] = W[tid];
    __syncthreads();

    const float s0 = sigma[0];
    if (tid < ZDIM && sigma[tid] != s0) atomicOr(&nonuniform, 1);

    // ---- zw[b,n,y] = sum_c z[b,n,c] * W[y,c], cooperative & coalesced ----
    // 4 threads per n-row, each covers 32 channels; 128 rows per pass, 4 passes.
    {
        const int part = tid & 3;       // which 32-channel chunk
        const int rown = tid >> 2;      // 0..127
        const float* Wp0 = W_s + part * 32;
        const float* Wp1 = W_s + ZDIM + part * 32;
#pragma unroll
        for (int pass = 0; pass < 4; ++pass) {
            const int n = rown + pass * 128;
            const float4* zr = (const float4*)(z + (size_t)(b * NN + n) * ZDIM + part * 32);
            float a0 = 0.0f, a1 = 0.0f;
#pragma unroll
            for (int j = 0; j < 8; ++j) {
                float4 v = zr[j];
                a0 = fmaf(v.x, Wp0[4 * j + 0], a0);
                a0 = fmaf(v.y, Wp0[4 * j + 1], a0);
                a0 = fmaf(v.z, Wp0[4 * j + 2], a0);
                a0 = fmaf(v.w, Wp0[4 * j + 3], a0);
                a1 = fmaf(v.x, Wp1[4 * j + 0], a1);
                a1 = fmaf(v.y, Wp1[4 * j + 1], a1);
                a1 = fmaf(v.z, Wp1[4 * j + 2], a1);
                a1 = fmaf(v.w, Wp1[4 * j + 3], a1);
            }
            // reduce the 4 partial chunks (lanes part=0..3 within the warp)
            a0 += __shfl_xor_sync(0xFFFFFFFFu, a0, 1);
            a0 += __shfl_xor_sync(0xFFFFFFFFu, a0, 2);
            a1 += __shfl_xor_sync(0xFFFFFFFFu, a1, 1);
            a1 += __shfl_xor_sync(0xFFFFFFFFu, a1, 2);
            if (part == 0) { zw0_s[n] = a0; zw1_s[n] = a1; }
        }
    }
    __syncthreads();

    // ---- main: each warp owns 2 m-points ----
    const int wid  = tid >> 5;
    const int lane = tid & 31;
    const int m0 = mbase + wid * 2;
    const int m1 = m0 + 1;
    const float x0 = x[b * MM + m0];
    const float x1 = x[b * MM + m1];

    float a00 = 0.f, a01 = 0.f, a10 = 0.f, a11 = 0.f;

    if (!nonuniform) {
        const float coef = -0.5f * __expf(-2.0f * s0);
#pragma unroll 4
        for (int i = lane; i < NN; i += 32) {
            const float ti = t_s[i];
            const float w0 = zw0_s[i];
            const float w1 = zw1_s[i];
            const float d0 = x0 - ti;
            const float d1 = x1 - ti;
            const float e0 = __expf(coef * d0 * d0);
            const float e1 = __expf(coef * d1 * d1);
            a00 = fmaf(e0, w0, a00);
            a01 = fmaf(e0, w1, a01);
            a10 = fmaf(e1, w0, a10);
            a11 = fmaf(e1, w1, a11);
        }
    } else {
        // general path: per-channel RBF length scales (correct for any sigma)
        for (int i = 0; i < NN; ++i) {
            const float d0 = x0 - t_s[i], d20 = d0 * d0;
            const float d1 = x1 - t_s[i], d21 = d1 * d1;
            const float* zr = z + (size_t)(b * NN + i) * ZDIM;
#pragma unroll
            for (int j = 0; j < ZDIM / 32; ++j) {
                const int   c   = lane + 32 * j;
                const float inv = __expf(-sigma[c]);      // 1/scale
                const float q   = -0.5f * inv * inv;
                const float e0  = __expf(q * d20);
                const float e1  = __expf(q * d21);
                const float zk  = zr[c];
                const float w0  = W_s[c];
                const float w1  = W_s[ZDIM + c];
                a00 = fmaf(zk * e0, w0, a00);
                a01 = fmaf(zk * e0, w1, a01);
                a10 = fmaf(zk * e1, w0, a10);
                a11 = fmaf(zk * e1, w1, a11);
            }
        }
    }

#pragma unroll
    for (int o = 16; o; o >>= 1) {
        a00 += __shfl_xor_sync(0xFFFFFFFFu, a00, o);
        a01 += __shfl_xor_sync(0xFFFFFFFFu, a01, o);
        a10 += __shfl_xor_sync(0xFFFFFFFFu, a10, o);
        a11 += __shfl_xor_sync(0xFFFFFFFFu, a11, o);
    }
    if (lane == 0) {
        const float b0 = bias[0], b1 = bias[1];
        out[(b * MM + m0) * YDIM + 0] = a00 + b0;
        out[(b * MM + m0) * YDIM + 1] = a01 + b1;
        out[(b * MM + m1) * YDIM + 0] = a10 + b0;
        out[(b * MM + m1) * YDIM + 1] = a11 + b1;
    }
}

// ---------------------------------------------------------------------------
extern "C" void kernel_launch(void* const* d_in, const int* in_sizes, int n_in,
                              void* d_out, int out_size) {
    const float* t     = (const float*)d_in[0];
    const float* z     = (const float*)d_in[1];
    const float* x     = (const float*)d_in[2];
    const float* sigma = (const float*)d_in[3];
    const float* W     = (const float*)d_in[4];
    const float* bias  = (const float*)d_in[5];
    float* out = (float*)d_out;

    decoder_fused_kernel<<<BB * GPB, NTHREADS>>>(t, z, x, sigma, W, bias, out);
}

// round 3
// speedup vs baseline: 1.7516x; 1.7516x over previous
#include <cuda_runtime.h>
#include <cuda_bf16.h>

// Decoder_2430951489916 — N-chunk decomposition with atomic accumulation.
//   B=4, N=512, M=512, ZD=128, YD=2, XD=1
// out[b,m,y] = b_y + sum_n sum_c W[y,c]*z[b,n,c]*exp(-0.5*((x_m-t_n)*exp(-sigma_c))^2)
// Fast path (all sigma equal — true for bench inputs):
//   out[b,m,y] = b_y + sum_n exp(coef*(x_m-t_n)^2) * zw[b,n,y],  zw = z @ W^T.
//
// Round-2 lesson: z must be read exactly ONCE across the grid (16x block
// redundancy exposed DRAM latency with only 64 blocks). Here each block owns
// one (batch, 8-row n-chunk): it reads its 8 z rows coalesced (1 MB total
// grid-wide), builds its zw chunk, then accumulates partial sums for ALL m of
// its batch into out via atomicAdd. 256 blocks -> full chip residency.

#define BB 4
#define NN 512
#define MM 512
#define ZDIM 128
#define YDIM 2
#define CHUNK 8
#define NCHUNKS (NN / CHUNK)     // 64
#define NTHREADS 256

__device__ float g_coef;
__device__ int   g_nonuniform;

// ---------------------------------------------------------------------------
// K1: out = bias (atomicAdd target), sigma uniformity flag + fast-path coef.
// ---------------------------------------------------------------------------
__global__ __launch_bounds__(512) void init_kernel(const float* __restrict__ sigma,
                                                   const float* __restrict__ bias,
                                                   float* __restrict__ out) {
    __shared__ int flag;
    const int tid = threadIdx.x;
    if (tid == 0) flag = 0;
    __syncthreads();

    const float s0 = sigma[0];
    if (tid < ZDIM && sigma[tid] != s0) atomicOr(&flag, 1);

    const float b0 = bias[0], b1 = bias[1];
    for (int i = tid; i < BB * MM; i += 512) {
        out[2 * i + 0] = b0;
        out[2 * i + 1] = b1;
    }
    __syncthreads();
    if (tid == 0) {
        g_nonuniform = flag;
        g_coef = -0.5f * __expf(-2.0f * s0);
    }
}

// ---------------------------------------------------------------------------
// K2: one block per (batch, n-chunk). 8 warps: warp w builds zw for row w of
// the chunk (coalesced float4 z read + warp reduce). Then each thread owns
// m-points {tid, tid+256} and accumulates over the 8 chunk rows, atomicAdd
// into out.
// ---------------------------------------------------------------------------
__global__ __launch_bounds__(NTHREADS) void decoder_chunk_kernel(
    const float* __restrict__ t,
    const float* __restrict__ z,
    const float* __restrict__ x,
    const float* __restrict__ sigma,
    const float* __restrict__ W,
    float* __restrict__ out) {
    __shared__ float t_s[CHUNK];
    __shared__ float zw0_s[CHUNK];
    __shared__ float zw1_s[CHUNK];
    __shared__ float W_s[YDIM * ZDIM];   // general path only
    __shared__ float q_s[ZDIM];          // general path only

    const int tid   = threadIdx.x;
    const int wid   = tid >> 5;          // 0..7
    const int lane  = tid & 31;
    const int b     = blockIdx.x / NCHUNKS;
    const int chunk = blockIdx.x % NCHUNKS;
    const int n0    = chunk * CHUNK;

    // stage small things (both paths)
    if (tid < YDIM * ZDIM) W_s[tid] = W[tid];
    if (tid < CHUNK)       t_s[tid] = t[b * NN + n0 + tid];   // XD == 1
    if (tid < ZDIM) {
        const float inv = __expf(-sigma[tid]);
        q_s[tid] = -0.5f * inv * inv;
    }

    // ---- zw chunk: warp `wid` handles row n0+wid. 32 lanes x float4 = 128 ch.
    {
        const float4* zp = (const float4*)(z + (size_t)(b * NN + n0 + wid) * ZDIM);
        const float4  v  = zp[lane];
        const float4  w0 = ((const float4*)W)[lane];          // W row 0
        const float4  w1 = ((const float4*)W)[32 + lane];     // W row 1
        float a0 = v.x * w0.x;  a0 = fmaf(v.y, w0.y, a0);
        a0 = fmaf(v.z, w0.z, a0); a0 = fmaf(v.w, w0.w, a0);
        float a1 = v.x * w1.x;  a1 = fmaf(v.y, w1.y, a1);
        a1 = fmaf(v.z, w1.z, a1); a1 = fmaf(v.w, w1.w, a1);
#pragma unroll
        for (int o = 16; o; o >>= 1) {
            a0 += __shfl_xor_sync(0xFFFFFFFFu, a0, o);
            a1 += __shfl_xor_sync(0xFFFFFFFFu, a1, o);
        }
        if (lane == 0) { zw0_s[wid] = a0; zw1_s[wid] = a1; }
    }
    __syncthreads();

    // ---- per-thread: two m-points over the 8 chunk rows ----
    const int m0 = tid;
    const int m1 = tid + NTHREADS;
    const float xm0 = x[b * MM + m0];
    const float xm1 = x[b * MM + m1];

    float s00 = 0.f, s01 = 0.f, s10 = 0.f, s11 = 0.f;

    if (!g_nonuniform) {
        const float coef = g_coef;
#pragma unroll
        for (int n = 0; n < CHUNK; ++n) {
            const float tn = t_s[n];
            const float w0 = zw0_s[n];
            const float w1 = zw1_s[n];
            const float d0 = xm0 - tn;
            const float d1 = xm1 - tn;
            const float e0 = __expf(coef * d0 * d0);
            const float e1 = __expf(coef * d1 * d1);
            s00 = fmaf(e0, w0, s00);  s01 = fmaf(e0, w1, s01);
            s10 = fmaf(e1, w0, s10);  s11 = fmaf(e1, w1, s11);
        }
    } else {
        // general path: per-channel length scales (correct for any sigma)
        for (int n = 0; n < CHUNK; ++n) {
            const float tn  = t_s[n];
            const float d0  = xm0 - tn, d20 = d0 * d0;
            const float d1  = xm1 - tn, d21 = d1 * d1;
            const float* zr = z + (size_t)(b * NN + n0 + n) * ZDIM;
            for (int c = 0; c < ZDIM; ++c) {
                const float q  = q_s[c];
                const float zc = zr[c];            // warp-uniform -> broadcast
                const float w0 = W_s[c];
                const float w1 = W_s[ZDIM + c];
                const float e0 = zc * __expf(q * d20);
                const float e1 = zc * __expf(q * d21);
                s00 = fmaf(e0, w0, s00);  s01 = fmaf(e0, w1, s01);
                s10 = fmaf(e1, w0, s10);  s11 = fmaf(e1, w1, s11);
            }
        }
    }

    float* o0 = out + (size_t)(b * MM + m0) * YDIM;
    float* o1 = out + (size_t)(b * MM + m1) * YDIM;
    atomicAdd(o0 + 0, s00);
    atomicAdd(o0 + 1, s01);
    atomicAdd(o1 + 0, s10);
    atomicAdd(o1 + 1, s11);
}

// ---------------------------------------------------------------------------
extern "C" void kernel_launch(void* const* d_in, const int* in_sizes, int n_in,
                              void* d_out, int out_size) {
    const float* t     = (const float*)d_in[0];
    const float* z     = (const float*)d_in[1];
    const float* x     = (const float*)d_in[2];
    const float* sigma = (const float*)d_in[3];
    const float* W     = (const float*)d_in[4];
    const float* bias  = (const float*)d_in[5];
    float* out = (float*)d_out;

    init_kernel<<<1, 512>>>(sigma, bias, out);
    decoder_chunk_kernel<<<BB * NCHUNKS, NTHREADS>>>(t, z, x, sigma, W, out);
}

// round 4
// speedup vs baseline: 1.9706x; 1.1250x over previous
#include <cuda_runtime.h>
#include <cstdint>

// Decoder_2430951489916 — single fused kernel, factorized exp + f32x2 + hybrid MUFU/poly.
//   B=4, N=512, M=512, ZD=128, YD=2, XD=1
// out[b,m,y] = b_y + sum_n sum_c W[y,c]*z[b,n,c]*exp(-0.5*((x_m-t_n)*exp(-sigma_c))^2)
//
// Fast path (uniform sigma; true for bench):
//   exp(c(x-t)^2) = exp(c x^2) * exp(c t^2) * exp2(K*x*t),  K = -2c*log2(e), c = -0.5*exp(-2*sigma0)
//   zw'_n = (z_n @ W^T) * exp(c t_n^2)   (folded once per n)
//   out[b,m,y] = bias_y + exp(c x_m^2) * sum_n exp2((K x_m) * t_n) * zw'_{n,y}
// Inner unit: 1 packed mul (arg, shared t) + EX2 + 2 packed fma accum -> ~1.5 fma-pipe + 1 MUFU/exp.
// 2 of 8 iterations use an FMA-pipe exp2 polynomial instead of MUFU (pipe balancing).

#define BB 4
#define NN 512
#define MM 512
#define ZDIM 128
#define YDIM 2
#define CHUNK 8
#define NCHUNKS (NN / CHUNK)        // 64
#define NTHREADS 256
#define GRID (BB * NCHUNKS)         // 256

typedef unsigned long long u64;

__device__ volatile int g_flag;     // out-initialized release flag (self-resetting)
__device__ int g_done;

// ---- f32x2 helpers -------------------------------------------------------
__device__ __forceinline__ u64 pk(float lo, float hi) {
    u64 r; asm("mov.b64 %0,{%1,%2};" : "=l"(r) : "f"(lo), "f"(hi)); return r;
}
__device__ __forceinline__ void upk(float& lo, float& hi, u64 v) {
    asm("mov.b64 {%0,%1},%2;" : "=f"(lo), "=f"(hi) : "l"(v));
}
__device__ __forceinline__ u64 pku(unsigned lo, unsigned hi) {
    u64 r; asm("mov.b64 %0,{%1,%2};" : "=l"(r) : "r"(lo), "r"(hi)); return r;
}
__device__ __forceinline__ void upki(unsigned& lo, unsigned& hi, u64 v) {
    asm("mov.b64 {%0,%1},%2;" : "=r"(lo), "=r"(hi) : "l"(v));
}
__device__ __forceinline__ u64 mul2(u64 a, u64 b) {
    u64 r; asm("mul.rn.f32x2 %0,%1,%2;" : "=l"(r) : "l"(a), "l"(b)); return r;
}
__device__ __forceinline__ u64 add2(u64 a, u64 b) {
    u64 r; asm("add.rn.f32x2 %0,%1,%2;" : "=l"(r) : "l"(a), "l"(b)); return r;
}
__device__ __forceinline__ u64 fma2(u64 a, u64 b, u64 c) {
    u64 r; asm("fma.rn.f32x2 %0,%1,%2,%3;" : "=l"(r) : "l"(a), "l"(b), "l"(c)); return r;
}
__device__ __forceinline__ float ex2(float x) {
    float r; asm("ex2.approx.ftz.f32 %0,%1;" : "=f"(r) : "f"(x)); return r;
}

// ---------------------------------------------------------------------------
__global__ __launch_bounds__(NTHREADS) void decoder_fused(
    const float* __restrict__ t,
    const float* __restrict__ z,
    const float* __restrict__ x,
    const float* __restrict__ sigma,
    const float* __restrict__ W,
    const float* __restrict__ bias,
    float* __restrict__ out) {
    __shared__ float2 td_s[CHUNK];            // (t_n, t_n)
    __shared__ float2 w0d_s[CHUNK];           // (zw0'_n, zw0'_n)
    __shared__ float2 w1d_s[CHUNK];           // (zw1'_n, zw1'_n)
    __shared__ float  t_s[CHUNK], zw0_s[CHUNK], zw1_s[CHUNK];  // unprimed (fallback)
    __shared__ float  W_s[YDIM * ZDIM];       // general path
    __shared__ float  q_s[ZDIM];              // general path
    __shared__ int    nonuniform;

    const int tid   = threadIdx.x;
    const int wid   = tid >> 5;
    const int lane  = tid & 31;
    const int b     = blockIdx.x / NCHUNKS;
    const int chunk = blockIdx.x % NCHUNKS;
    const int n0    = chunk * CHUNK;

    // ---- block 0 also initializes out = bias, then releases the flag ----
    if (blockIdx.x == 0) {
        const float b0 = bias[0], b1 = bias[1];
        for (int i = tid; i < BB * MM; i += NTHREADS) {
            out[2 * i + 0] = b0;
            out[2 * i + 1] = b1;
        }
        __syncthreads();
        if (tid == 0) { __threadfence(); atomicExch((int*)&g_flag, 1); }
    }

    if (tid == 0) nonuniform = 0;
    if (tid < YDIM * ZDIM) W_s[tid] = W[tid];
    const float s0 = sigma[0];
    if (tid < ZDIM) {
        const float sv = sigma[tid];
        if (sv != s0) atomicOr(&nonuniform, 1);
        const float inv = __expf(-sv);
        q_s[tid] = -0.5f * inv * inv;
    }
    const float coef = -0.5f * __expf(-2.0f * s0);

    // ---- zw' chunk: warp `wid` handles row n0+wid (coalesced float4 z read) ----
    {
        const float4* zp = (const float4*)(z + (size_t)(b * NN + n0 + wid) * ZDIM);
        const float4  v  = zp[lane];
        const float4  w0 = ((const float4*)W)[lane];
        const float4  w1 = ((const float4*)W)[32 + lane];
        float a0 = v.x * w0.x;  a0 = fmaf(v.y, w0.y, a0);
        a0 = fmaf(v.z, w0.z, a0); a0 = fmaf(v.w, w0.w, a0);
        float a1 = v.x * w1.x;  a1 = fmaf(v.y, w1.y, a1);
        a1 = fmaf(v.z, w1.z, a1); a1 = fmaf(v.w, w1.w, a1);
#pragma unroll
        for (int o = 16; o; o >>= 1) {
            a0 += __shfl_xor_sync(0xFFFFFFFFu, a0, o);
            a1 += __shfl_xor_sync(0xFFFFFFFFu, a1, o);
        }
        if (lane == 0) {
            const float tn = t[b * NN + n0 + wid];
            const float et = __expf(coef * tn * tn);
            t_s[wid]   = tn;  zw0_s[wid] = a0;  zw1_s[wid] = a1;
            td_s[wid]  = make_float2(tn, tn);
            w0d_s[wid] = make_float2(a0 * et, a0 * et);
            w1d_s[wid] = make_float2(a1 * et, a1 * et);
        }
    }
    __syncthreads();

    // ---- per-thread: m-pair (tid, tid+256) over 8 chunk rows ----
    const int   m0  = tid;
    const int   m1  = tid + NTHREADS;
    const float x0  = x[b * MM + m0];
    const float x1  = x[b * MM + m1];

    float s00, s01, s10, s11;

    if (!nonuniform) {
        float tmax = 0.0f;
#pragma unroll
        for (int n = 0; n < CHUNK; ++n) tmax = fmaxf(tmax, fabsf(t_s[n]));
        const float xm   = fmaxf(fabsf(x0), fabsf(x1));
        const float rad  = tmax + xm;
        const bool  safe = (fabsf(coef) * rad * rad) < 80.0f;

        if (safe) {
            const float KK  = -2.0f * coef * 1.44269504088896f;
            const u64   hp  = pk(KK * x0, KK * x1);
            const float Em0 = __expf(coef * x0 * x0);
            const float Em1 = __expf(coef * x1 * x1);
            // packed poly constants (2^f on [-0.5,0.5], deg 5)
            const u64 MG2 = pk( 12582912.0f,  12582912.0f);   // 1.5*2^23
            const u64 NG2 = pk(-12582912.0f, -12582912.0f);
            const u64 M1  = pk(-1.0f, -1.0f);
            const u64 C5  = pk(0.00133335581f, 0.00133335581f);
            const u64 C4  = pk(0.00961812911f, 0.00961812911f);
            const u64 C3  = pk(0.0555041087f,  0.0555041087f);
            const u64 C2  = pk(0.240226507f,   0.240226507f);
            const u64 C1  = pk(0.693147180f,   0.693147180f);
            const u64 C0  = pk(1.0f, 1.0f);

            u64 sc0 = pk(0.0f, 0.0f);
            u64 sc1 = pk(0.0f, 0.0f);
#pragma unroll
            for (int n = 0; n < CHUNK; ++n) {
                const u64 tp = *(const u64*)&td_s[n];
                const u64 a  = mul2(hp, tp);
                u64 e;
                if (n < 6) {
                    // MUFU path
                    float a0f, a1f; upk(a0f, a1f, a);
                    e = pk(ex2(a0f), ex2(a1f));
                } else {
                    // FMA-pipe exp2 polynomial path
                    const u64 tb = add2(a, MG2);           // arg + magic
                    const u64 rk = add2(tb, NG2);          // round(arg) as float
                    const u64 f  = fma2(rk, M1, a);        // frac = arg - round
                    unsigned i0, i1; upki(i0, i1, tb);
                    const unsigned CC = (unsigned)(127u - 0x4B400000u);
                    const unsigned sb0 = (i0 + CC) << 23;  // 2^k bits
                    const unsigned sb1 = (i1 + CC) << 23;
                    u64 p = fma2(f, C5, C4);
                    p = fma2(p, f, C3);
                    p = fma2(p, f, C2);
                    p = fma2(p, f, C1);
                    p = fma2(p, f, C0);
                    e = mul2(p, pku(sb0, sb1));
                }
                sc0 = fma2(e, *(const u64*)&w0d_s[n], sc0);
                sc1 = fma2(e, *(const u64*)&w1d_s[n], sc1);
            }
            upk(s00, s10, sc0);
            upk(s01, s11, sc1);
            s00 *= Em0; s01 *= Em0;
            s10 *= Em1; s11 *= Em1;
        } else {
            // exact direct form (magnitude guard tripped — never on bench data)
            s00 = s01 = s10 = s11 = 0.0f;
#pragma unroll
            for (int n = 0; n < CHUNK; ++n) {
                const float tn = t_s[n];
                const float w0 = zw0_s[n], w1 = zw1_s[n];
                const float d0 = x0 - tn,  d1 = x1 - tn;
                const float e0 = __expf(coef * d0 * d0);
                const float e1 = __expf(coef * d1 * d1);
                s00 = fmaf(e0, w0, s00);  s01 = fmaf(e0, w1, s01);
                s10 = fmaf(e1, w0, s10);  s11 = fmaf(e1, w1, s11);
            }
        }
    } else {
        // general path: per-channel length scales (correct for any sigma)
        s00 = s01 = s10 = s11 = 0.0f;
        for (int n = 0; n < CHUNK; ++n) {
            const float tn  = t_s[n];
            const float d20 = (x0 - tn) * (x0 - tn);
            const float d21 = (x1 - tn) * (x1 - tn);
            const float* zr = z + (size_t)(b * NN + n0 + n) * ZDIM;
            for (int c = 0; c < ZDIM; ++c) {
                const float q  = q_s[c];
                const float zc = zr[c];
                const float w0 = W_s[c];
                const float w1 = W_s[ZDIM + c];
                const float e0 = zc * __expf(q * d20);
                const float e1 = zc * __expf(q * d21);
                s00 = fmaf(e0, w0, s00);  s01 = fmaf(e0, w1, s01);
                s10 = fmaf(e1, w0, s10);  s11 = fmaf(e1, w1, s11);
            }
        }
    }

    // ---- gate on out-init, then accumulate ----
    if (tid == 0) { while (g_flag == 0) { } }
    __syncthreads();

    float* o0 = out + (size_t)(b * MM + m0) * YDIM;
    float* o1 = out + (size_t)(b * MM + m1) * YDIM;
    atomicAdd(o0 + 0, s00);
    atomicAdd(o0 + 1, s01);
    atomicAdd(o1 + 0, s10);
    atomicAdd(o1 + 1, s11);

    // ---- self-resetting completion (graph-replay safe) ----
    __syncthreads();
    if (tid == 0) {
        __threadfence();
        if (atomicAdd(&g_done, 1) == GRID - 1) {
            atomicExch(&g_done, 0);
            atomicExch((int*)&g_flag, 0);
        }
    }
}

// ---------------------------------------------------------------------------
extern "C" void kernel_launch(void* const* d_in, const int* in_sizes, int n_in,
                              void* d_out, int out_size) {
    const float* t     = (const float*)d_in[0];
    const float* z     = (const float*)d_in[1];
    const float* x     = (const float*)d_in[2];
    const float* sigma = (const float*)d_in[3];
    const float* W     = (const float*)d_in[4];
    const float* bias  = (const float*)d_in[5];
    float* out = (float*)d_out;

    decoder_fused<<<GRID, NTHREADS>>>(t, z, x, sigma, W, bias, out);
}